// round 9
// baseline (speedup 1.0000x reference)
#include <cuda_runtime.h>
#include <cuda_fp16.h>
#include <cstdint>

// NeiAttention, factored 4-kernel form (round 9).
// K0: W fp32 -> fp16 (g_w16) once.
// K1: y = x @ W            fp16 MMA, W via cp.async (fp16), B frags via ldmatrix.trans
// K2: logits/softmax/z     streams A once (fp32), writes z as fp16   [at DRAM roofline]
// K3: out = z @ W^T + b    fp16 MMA, z+W staged purely by cp.async

__device__ float  g_y[16384 * 192];
__device__ __half g_z16[16384 * 192];
__device__ __half g_w16[128 * 192];

__device__ __forceinline__ uint32_t smem_u32(const void* p) {
    uint32_t a;
    asm("{ .reg .u64 t; cvta.to.shared.u64 t, %1; cvt.u32.u64 %0, t; }" : "=r"(a) : "l"(p));
    return a;
}
__device__ __forceinline__ uint32_t pack_f16x2(float lo, float hi) {
    uint32_t r;
    asm("cvt.rn.f16x2.f32 %0, %1, %2;" : "=r"(r) : "f"(hi), "f"(lo));
    return r;
}
__device__ __forceinline__ void ldsm4(uint32_t r[4], uint32_t addr) {
    asm volatile("ldmatrix.sync.aligned.m8n8.x4.shared.b16 {%0,%1,%2,%3}, [%4];"
                 : "=r"(r[0]), "=r"(r[1]), "=r"(r[2]), "=r"(r[3]) : "r"(addr));
}
__device__ __forceinline__ void ldsm4t(uint32_t r[4], uint32_t addr) {
    asm volatile("ldmatrix.sync.aligned.m8n8.x4.trans.shared.b16 {%0,%1,%2,%3}, [%4];"
                 : "=r"(r[0]), "=r"(r[1]), "=r"(r[2]), "=r"(r[3]) : "r"(addr));
}
__device__ __forceinline__ void mma_f16(float d[4], const uint32_t a[4],
                                        uint32_t b0, uint32_t b1) {
    asm volatile(
        "mma.sync.aligned.m16n8k16.row.col.f32.f16.f16.f32 "
        "{%0,%1,%2,%3}, {%4,%5,%6,%7}, {%8,%9}, {%0,%1,%2,%3};"
        : "+f"(d[0]), "+f"(d[1]), "+f"(d[2]), "+f"(d[3])
        : "r"(a[0]), "r"(a[1]), "r"(a[2]), "r"(a[3]), "r"(b0), "r"(b1));
}
__device__ __forceinline__ void cpa16(uint32_t dst, const void* src) {
    asm volatile("cp.async.cg.shared.global [%0], [%1], 16;" :: "r"(dst), "l"(src));
}
__device__ __forceinline__ void cp_commit() { asm volatile("cp.async.commit_group;" ::: "memory"); }
template <int N>
__device__ __forceinline__ void cp_wait() { asm volatile("cp.async.wait_group %0;" :: "n"(N) : "memory"); }
__device__ __forceinline__ float shflx(float v, int m) { return __shfl_xor_sync(0xffffffffu, v, m); }

// ============================ K0: W -> fp16 ============================
__global__ __launch_bounds__(256, 1)
void k0_wcvt(const float* __restrict__ W1_w)
{
    int i = blockIdx.x * 256 + threadIdx.x;      // 12288 threads, 1 float2 each
    float2 v = ((const float2*)W1_w)[i];
    ((uint32_t*)g_w16)[i] = pack_f16x2(v.x, v.y);
}

// ============================ K1: y = x @ W ============================
// 256 CTAs x 64 rows, 256 thr (warp grid 2x4, warp tile 32x48).
// A = x rows fp16 (stride 272B). B = W natural [d][k'] fp16 (stride 400B), trans-ldmatrix.
#define K1_XH   0         // 64*68  = 4352 w
#define K1_WH   4352      // 128*100 = 12800 w
#define K1_WORDS 17152
#define K1_BYTES (K1_WORDS * 4)   // 68,608 B

__global__ __launch_bounds__(256, 2)
void k1_y(const float* __restrict__ x)
{
    extern __shared__ float sm[];
    const uint32_t sb = smem_u32(sm);
    const int tid = threadIdx.x;
    const int wid = tid >> 5, lid = tid & 31;
    const int g = lid >> 2, t4 = lid & 3;
    const int sel = lid >> 3, lr = lid & 7;
    const int wm = wid >> 2, wn = wid & 3;

    // stage W fp16 via cp.async (natural [d][k'], stride 100 words)
    {
        #pragma unroll
        for (int it = 0; it < 12; it++) {
            int idx = tid + it * 256;            // 0..3071 = r*24 + c
            int r = idx / 24, c = idx - r * 24;
            cpa16(sb + K1_WH * 4 + (uint32_t)(r * 100 + c * 4) * 4u,
                  g_w16 + r * 192 + c * 8);
        }
        cp_commit();
    }
    // stage x tile (64 rows, fp16, stride 68 words) — overlaps the async W load
    {
        const float4* xp = (const float4*)(x + (size_t)blockIdx.x * 64 * 128);
        #pragma unroll
        for (int it = 0; it < 8; it++) {
            int idx = tid + it * 256;            // r*32 + c
            int r = idx >> 5, c = idx & 31;
            float4 v = xp[idx];
            uint2 w;
            w.x = pack_f16x2(v.x, v.y);
            w.y = pack_f16x2(v.z, v.w);
            *(uint2*)((uint32_t*)sm + K1_XH + r * 68 + 2 * c) = w;
        }
    }
    cp_wait<0>();
    __syncthreads();

    // A fragment addrs (non-trans)
    uint32_t aA[2];
    #pragma unroll
    for (int i = 0; i < 2; i++)
        aA[i] = sb + K1_XH * 4 + (uint32_t)(wm * 32 + i * 16 + (sel & 1) * 8 + lr) * 272u
                + (uint32_t)(sel >> 1) * 16u;
    // B fragment addrs (trans)
    const int drow = (lid & 7) + ((lid >> 3) & 1) * 8;
    const int kgrp = (lid >> 4);
    uint32_t bT[3];
    #pragma unroll
    for (int jp = 0; jp < 3; jp++)
        bT[jp] = sb + K1_WH * 4 + (uint32_t)drow * 400u
                 + (uint32_t)(wn * 48 + jp * 16 + kgrp * 8) * 2u;

    float acc[2][6][4];
    #pragma unroll
    for (int i = 0; i < 2; i++)
        #pragma unroll
        for (int j = 0; j < 6; j++)
            #pragma unroll
            for (int q = 0; q < 4; q++) acc[i][j][q] = 0.f;

    #pragma unroll
    for (int ks = 0; ks < 8; ks++) {             // K = 128 (d)
        uint32_t a0[4], a1[4];
        ldsm4(a0, aA[0] + ks * 32);
        ldsm4(a1, aA[1] + ks * 32);
        #pragma unroll
        for (int jp = 0; jp < 3; jp++) {
            uint32_t bt[4];
            ldsm4t(bt, bT[jp] + ks * 6400);      // +16 d-rows * 400 B
            mma_f16(acc[0][2 * jp],     a0, bt[0], bt[1]);
            mma_f16(acc[0][2 * jp + 1], a0, bt[2], bt[3]);
            mma_f16(acc[1][2 * jp],     a1, bt[0], bt[1]);
            mma_f16(acc[1][2 * jp + 1], a1, bt[2], bt[3]);
        }
    }

    #pragma unroll
    for (int i = 0; i < 2; i++) {
        int row = blockIdx.x * 64 + wm * 32 + i * 16 + g;
        #pragma unroll
        for (int j = 0; j < 6; j++) {
            int col = wn * 48 + j * 8 + 2 * t4;
            float2 w0 = { acc[i][j][0], acc[i][j][1] };
            float2 w1 = { acc[i][j][2], acc[i][j][3] };
            *(float2*)(g_y + (size_t)row * 192 + col)       = w0;
            *(float2*)(g_y + (size_t)(row + 8) * 192 + col) = w1;
        }
    }
}

// ============== K2: logits, softmax, z (fp16 out) — unchanged, at roofline ==============
#define K2_AST  196
#define K2_SA   0         // 128*196 = 25088 w
#define K2_SY   25088     // 8*192 = 1536 w
#define K2_AL   26624     // 128
#define K2_SE   26752     // 128
#define K2_WORDS 26880
#define K2_BYTES (K2_WORDS * 4)   // 107,520 B -> 2 CTAs/SM

__global__ __launch_bounds__(256, 2)
void k2_attn(const float* __restrict__ x_nei_rel,
             const float* __restrict__ x_nei_node)
{
    extern __shared__ float sm[];
    const uint32_t sb = smem_u32(sm);
    float* sA  = sm + K2_SA;
    float* sY  = sm + K2_SY;
    float* sAl = sm + K2_AL;
    float* sE  = sm + K2_SE;
    const uint32_t aU = sb + K2_SA * 4, yU = sb + K2_SY * 4;

    const int tid = threadIdx.x;
    const int b = blockIdx.y, nc = blockIdx.x;
    const size_t row0  = (size_t)b * 512 + (size_t)nc * 128;
    const int    nbase = b * 32 + nc * 8;

    // group 0: rel (k 0..63) + node k 64..95 + y rows
    {
        const float4* rp = (const float4*)(x_nei_rel + row0 * 64);
        #pragma unroll
        for (int it = 0; it < 8; it++) {
            int idx = tid + it * 256;
            int r = idx >> 4, c = idx & 15;
            cpa16(aU + (uint32_t)(r * K2_AST + c * 4) * 4u, rp + r * 16 + c);
        }
        const float4* np = (const float4*)(x_nei_node + row0 * 128);
        #pragma unroll
        for (int it = 0; it < 4; it++) {
            int idx = tid + it * 256;
            int r = idx >> 3, c = idx & 7;
            cpa16(aU + (uint32_t)(r * K2_AST + 64 + c * 4) * 4u, np + r * 32 + c);
        }
        #pragma unroll
        for (int it = 0; it < 2; it++) {
            int idx = tid + it * 256;
            if (idx < 384)
                cpa16(yU + (uint32_t)idx * 16u, g_y + (size_t)nbase * 192 + idx * 4);
        }
        cp_commit();
        // group 1: node k 96..191
        #pragma unroll
        for (int it = 0; it < 12; it++) {
            int idx = tid + it * 256;
            int r = idx / 24, c = idx - r * 24;
            cpa16(aU + (uint32_t)(r * K2_AST + 96 + c * 4) * 4u, np + r * 32 + 8 + c);
        }
        cp_commit();
    }

    // dots
    const int r = tid >> 1, h = tid & 1;
    float s = 0.f;
    cp_wait<1>();
    __syncthreads();
    {
        const float* ar = sA + r * K2_AST + h * 48;
        const float* yr = sY + (r >> 4) * 192 + h * 48;
        #pragma unroll
        for (int k = 0; k < 48; k++) s += ar[k] * yr[k];
    }
    cp_wait<0>();
    __syncthreads();
    {
        const float* ar = sA + r * K2_AST + 96 + h * 48;
        const float* yr = sY + (r >> 4) * 192 + 96 + h * 48;
        #pragma unroll
        for (int k = 0; k < 48; k++) s += ar[k] * yr[k];
    }
    s += shflx(s, 1);
    if (h == 0) sAl[r] = s * 0.08838834764831845f;   // 1/sqrt(128)
    __syncthreads();

    // softmax over S=16
    float e = 0.f;
    if (tid < 128) {
        int base = tid & ~15;
        float m = -1e30f;
        #pragma unroll
        for (int q = 0; q < 16; q++) m = fmaxf(m, sAl[base + q]);
        e = __expf(sAl[tid] - m);
        sE[tid] = e;
    }
    __syncthreads();
    if (tid < 128) {
        int base = tid & ~15;
        float den = 0.f;
        #pragma unroll
        for (int q = 0; q < 16; q++) den += sE[base + q];
        sAl[tid] = e / den;
    }
    __syncthreads();

    // z[node][dim-pair] = sum_s alpha * a  -> fp16
    #pragma unroll
    for (int p = 0; p < 3; p++) {
        int u = tid + 256 * p;
        int node = u / 96;
        int dp   = u - node * 96;
        const float* ap = sA + (node * 16) * K2_AST + 2 * dp;
        const float* al = sAl + node * 16;
        float z0 = 0.f, z1 = 0.f;
        #pragma unroll
        for (int q = 0; q < 16; q++) {
            float2 av = *(const float2*)(ap + q * K2_AST);
            float  a  = al[q];
            z0 += a * av.x;
            z1 += a * av.y;
        }
        *(uint32_t*)(g_z16 + (size_t)(nbase + node) * 192 + 2 * dp) = pack_f16x2(z0, z1);
    }
}

// ============================ K3: out = z @ W^T + b ============================
// 256 CTAs x 64 rows, 256 thr. Entirely cp.async-staged (z fp16 + W fp16).
#define K3_ZH   0         // 64*100 = 6400 w
#define K3_WH   6400      // 128*100 = 12800 w
#define K3_WORDS 19200
#define K3_BYTES (K3_WORDS * 4)   // 76,800 B

__global__ __launch_bounds__(256, 2)
void k3_out(const float* __restrict__ W1_b,
            float* __restrict__ out)
{
    extern __shared__ float sm[];
    const uint32_t sb = smem_u32(sm);
    const int tid = threadIdx.x;
    const int wid = tid >> 5, lid = tid & 31;
    const int g = lid >> 2, t4 = lid & 3;
    const int sel = lid >> 3, lr = lid & 7;
    const int wm = wid >> 2, wn = wid & 3;

    // stage z rows (fp16) + W (fp16) in one async group
    {
        const __half* zp = g_z16 + (size_t)blockIdx.x * 64 * 192;
        #pragma unroll
        for (int it = 0; it < 6; it++) {
            int idx = tid + it * 256;            // r*24 + c
            int r = idx / 24, c = idx - r * 24;
            cpa16(sb + K3_ZH * 4 + (uint32_t)(r * 100 + c * 4) * 4u, zp + r * 192 + c * 8);
        }
        #pragma unroll
        for (int it = 0; it < 12; it++) {
            int idx = tid + it * 256;
            int r = idx / 24, c = idx - r * 24;
            cpa16(sb + K3_WH * 4 + (uint32_t)(r * 100 + c * 4) * 4u,
                  g_w16 + r * 192 + c * 8);
        }
        cp_commit();
    }
    cp_wait<0>();
    __syncthreads();

    uint32_t aA[2], bA[2];
    #pragma unroll
    for (int i = 0; i < 2; i++)
        aA[i] = sb + K3_ZH * 4 + (uint32_t)(wm * 32 + i * 16 + (sel & 1) * 8 + lr) * 400u
                + (uint32_t)(sel >> 1) * 16u;
    #pragma unroll
    for (int jp = 0; jp < 2; jp++)
        bA[jp] = sb + K3_WH * 4 + (uint32_t)(wn * 32 + jp * 16 + (sel >> 1) * 8 + lr) * 400u
                 + (uint32_t)(sel & 1) * 16u;

    float acc[2][4][4];
    #pragma unroll
    for (int i = 0; i < 2; i++)
        #pragma unroll
        for (int j = 0; j < 4; j++)
            #pragma unroll
            for (int q = 0; q < 4; q++) acc[i][j][q] = 0.f;

    #pragma unroll
    for (int ks = 0; ks < 12; ks++) {            // K = 192
        uint32_t a0[4], a1[4], b0[4], b1[4];
        ldsm4(a0, aA[0] + ks * 32);
        ldsm4(a1, aA[1] + ks * 32);
        ldsm4(b0, bA[0] + ks * 32);
        ldsm4(b1, bA[1] + ks * 32);
        mma_f16(acc[0][0], a0, b0[0], b0[1]);
        mma_f16(acc[0][1], a0, b0[2], b0[3]);
        mma_f16(acc[0][2], a0, b1[0], b1[1]);
        mma_f16(acc[0][3], a0, b1[2], b1[3]);
        mma_f16(acc[1][0], a1, b0[0], b0[1]);
        mma_f16(acc[1][1], a1, b0[2], b0[3]);
        mma_f16(acc[1][2], a1, b1[0], b1[1]);
        mma_f16(acc[1][3], a1, b1[2], b1[3]);
    }

    #pragma unroll
    for (int i = 0; i < 2; i++) {
        int row = blockIdx.x * 64 + wm * 32 + i * 16 + g;
        #pragma unroll
        for (int j = 0; j < 4; j++) {
            int col = wn * 32 + j * 8 + 2 * t4;
            float b0 = __ldg(W1_b + col), b1 = __ldg(W1_b + col + 1);
            float2 w0 = { acc[i][j][0] + b0, acc[i][j][1] + b1 };
            float2 w1 = { acc[i][j][2] + b0, acc[i][j][3] + b1 };
            *(float2*)(out + (size_t)row * 128 + col)       = w0;
            *(float2*)(out + (size_t)(row + 8) * 128 + col) = w1;
        }
    }
}

extern "C" void kernel_launch(void* const* d_in, const int* in_sizes, int n_in,
                              void* d_out, int out_size)
{
    const float* x          = (const float*)d_in[0];
    const float* x_nei_rel  = (const float*)d_in[1];
    const float* x_nei_node = (const float*)d_in[2];
    const float* W1_w       = (const float*)d_in[3];
    const float* W1_b       = (const float*)d_in[4];
    float* out = (float*)d_out;

    cudaFuncSetAttribute(k1_y,    cudaFuncAttributeMaxDynamicSharedMemorySize, K1_BYTES);
    cudaFuncSetAttribute(k2_attn, cudaFuncAttributeMaxDynamicSharedMemorySize, K2_BYTES);
    cudaFuncSetAttribute(k3_out,  cudaFuncAttributeMaxDynamicSharedMemorySize, K3_BYTES);

    k0_wcvt<<<48, 256>>>(W1_w);
    k1_y<<<256, 256, K1_BYTES>>>(x);
    k2_attn<<<dim3(4, 512), 256, K2_BYTES>>>(x_nei_rel, x_nei_node);
    k3_out<<<256, 256, K3_BYTES>>>(W1_b, out);
}